// round 6
// baseline (speedup 1.0000x reference)
#include <cuda_runtime.h>

// Problem constants (fixed by the dataset)
#define B_   4096
#define H_   256
#define R_   14              // rows per CTA
#define NCTA 293             // ceil(4096/14): 292 full + 1 partial (8 rows)
#define HS   18              // h2 row stride in floats (72B: 8B-aligned u64s, 2-way STS)

// ---------------------------------------------------------------------------
// Device scratch (no dynamic allocation allowed)
// ---------------------------------------------------------------------------
__device__ float4 g_packWhh[256 * 256];  // [k][j] -> (Whh_i, Whh_f, Whh_g, Whh_o)[j][k]
__device__ float4 g_packWih[3 * 256];    // [e][j]
__device__ float4 g_packBias[256];       // [j]    -> bih+bhh per gate
__device__ float  g_W2T[256 * 512];      // [k][j]
__device__ float  g_Wo1T[256 * 128];     // [k][j2]
__device__ float  g_W1T[7 * 256];        // [k][j]

// ---------------------------------------------------------------------------
// Prep kernel: transpose / gate-pack weights for coalesced LDG.128 streaming
// ---------------------------------------------------------------------------
__global__ void prep_kernel(const float* __restrict__ W1,
                            const float* __restrict__ W2,
                            const float* __restrict__ Wih,
                            const float* __restrict__ Whh,
                            const float* __restrict__ bih,
                            const float* __restrict__ bhh,
                            const float* __restrict__ Wo1)
{
    int k = blockIdx.x;    // 0..255
    int j = threadIdx.x;   // 0..255

    g_packWhh[k * 256 + j] = make_float4(Whh[(0   + j) * 256 + k],
                                         Whh[(256 + j) * 256 + k],
                                         Whh[(512 + j) * 256 + k],
                                         Whh[(768 + j) * 256 + k]);
    g_W2T[k * 512 + j]       = W2[(0   + j) * 256 + k];
    g_W2T[k * 512 + 256 + j] = W2[(256 + j) * 256 + k];
    if (j < 128) g_Wo1T[k * 128 + j] = Wo1[j * 256 + k];
    if (k < 7)   g_W1T[k * 256 + j] = W1[j * 7 + k];
    if (k < 3)   g_packWih[k * 256 + j] = make_float4(Wih[(0   + j) * 3 + k],
                                                      Wih[(256 + j) * 3 + k],
                                                      Wih[(512 + j) * 3 + k],
                                                      Wih[(768 + j) * 3 + k]);
    if (k == 0)  g_packBias[j] = make_float4(bih[0   + j] + bhh[0   + j],
                                             bih[256 + j] + bhh[256 + j],
                                             bih[512 + j] + bhh[512 + j],
                                             bih[768 + j] + bhh[768 + j]);
}

// ---------------------------------------------------------------------------
// Packed f32x2 helpers (sm_100+): doubles fp32 FMA throughput per issue
// ---------------------------------------------------------------------------
typedef unsigned long long u64;

__device__ __forceinline__ u64 fma2(u64 a, u64 b, u64 c) {
    u64 d;
    asm("fma.rn.f32x2 %0, %1, %2, %3;" : "=l"(d) : "l"(a), "l"(b), "l"(c));
    return d;
}
__device__ __forceinline__ u64 dup2(float x) {
    u64 d; unsigned xi = __float_as_uint(x);
    asm("mov.b64 %0, {%1, %2};" : "=l"(d) : "r"(xi), "r"(xi));
    return d;
}
__device__ __forceinline__ u64 pk(float lo, float hi) {
    u64 d;
    asm("mov.b64 %0, {%1, %2};" : "=l"(d)
        : "r"(__float_as_uint(lo)), "r"(__float_as_uint(hi)));
    return d;
}
__device__ __forceinline__ float2 unpk(u64 a) {
    unsigned lo, hi;
    asm("mov.b64 {%0, %1}, %2;" : "=r"(lo), "=r"(hi) : "l"(a));
    return make_float2(__uint_as_float(lo), __uint_as_float(hi));
}

__device__ __forceinline__ float sigmoidf_(float x) {
    return __fdividef(1.f, 1.f + __expf(-x));
}
// branch-free accurate tanh: 1 - 2/(e^{2x}+1); inf-safe at both ends, ~1e-6 err
__device__ __forceinline__ float tanhf_(float x) {
    float e = __expf(2.f * x);
    return 1.f - __fdividef(2.f, e + 1.f);
}

// ---------------------------------------------------------------------------
// Main persistent kernel: one CTA handles 14 batch rows end-to-end.
// Thread t owns hidden unit j=t (all 4 gates), rows packed as f32x2 pairs.
// ---------------------------------------------------------------------------
__global__ void __launch_bounds__(256, 2)
lstm_kernel(const float* __restrict__ meta,
            const float* __restrict__ b1,
            const float* __restrict__ b2,
            const float* __restrict__ bo1,
            const float* __restrict__ Wo2,
            const float* __restrict__ bo2,
            float* __restrict__ out,
            int T_eff)
{
    __shared__ __align__(16) float h2[2][256][HS]; // double-buffered h [buf][k][row]
    __shared__ __align__(16) float xs[3][16];      // [elem][row] current x (fed-back y)
    __shared__ float zb[14][132];                  // decoder hidden [row][j2] (padded)
    __shared__ float metas[14][8];                 // metadata rows (padded)
    __shared__ float wo2s[3 * 128];
    __shared__ float bo1s[128];
    __shared__ float bo2s[4];

    const int t    = threadIdx.x;
    const int row0 = blockIdx.x * R_;

    // ---- stage small tensors (row indices clamped for the partial last CTA) ----
    if (t < 112) {
        int r = t >> 3, e = t & 7;
        int g = row0 + r; if (g > B_ - 1) g = B_ - 1;
        metas[r][e] = (e < 7) ? meta[g * 7 + e] : 0.f;
    }
    if (t < 128) bo1s[t] = bo1[t];
    wo2s[t] = Wo2[t];
    if (t < 128) wo2s[256 + t] = Wo2[256 + t];
    if (t < 3)   bo2s[t] = bo2[t];
    if (t < 42) {
        int r = t / 3, o = t - 3 * (t / 3);
        int g = row0 + r; if (g > B_ - 1) g = B_ - 1;
        xs[o][r] = meta[g * 7 + o];   // x0 = metadata[:, :3]
    }
    __syncthreads();

    // ---- encoder layer 1: enc1 -> h2[1][t][r] ----
    {
        float a[R_];
        float bb = b1[t];
        #pragma unroll
        for (int r = 0; r < R_; r++) a[r] = bb;
        #pragma unroll
        for (int k = 0; k < 7; k++) {
            float w = g_W1T[k * 256 + t];
            #pragma unroll
            for (int r = 0; r < R_; r++) a[r] += metas[r][k] * w;
        }
        #pragma unroll
        for (int r = 0; r < R_; r++) h2[1][t][r] = fmaxf(a[r], 0.f);
    }
    __syncthreads();

    // ---- encoder layer 2: h0 -> h2[0], c0 in regs ----
    u64 c2[7];
    {
        u64 ha[7], ca[7];
        u64 bh = dup2(b2[t]), bc = dup2(b2[256 + t]);
        #pragma unroll
        for (int p = 0; p < 7; p++) { ha[p] = bh; ca[p] = bc; }
        const float* hrow = &h2[1][0][0];
        #pragma unroll 2
        for (int k = 0; k < 256; k++) {
            u64 wh = dup2(g_W2T[k * 512 + t]);
            u64 wc = dup2(g_W2T[k * 512 + 256 + t]);
            const u64* hp = reinterpret_cast<const u64*>(hrow + k * HS);
            #pragma unroll
            for (int p = 0; p < 7; p++) {
                u64 h = hp[p];
                ha[p] = fma2(h, wh, ha[p]);
                ca[p] = fma2(h, wc, ca[p]);
            }
        }
        // writes go to buffer 0 (readers were on buffer 1) -> no barrier needed here
        #pragma unroll
        for (int p = 0; p < 7; p++) {
            float2 hv = unpk(ha[p]);
            float2 cv = unpk(ca[p]);
            h2[0][t][2 * p]     = fmaxf(hv.x, 0.f);
            h2[0][t][2 * p + 1] = fmaxf(hv.y, 0.f);
            c2[p] = pk(fmaxf(cv.x, 0.f), fmaxf(cv.y, 0.f));
        }
    }
    __syncthreads();

    float* outp = out + (long)row0 * (T_eff * 3);
    int cur = 0;

    // =====================  LSTM scan  =====================
    for (int step = 0; step < T_eff; step++) {
        const int nxt = cur ^ 1;

        // ---- gate accumulation: gates[j] = bias + x.Wih + h.Whh ----
        u64 ai[7], af[7], ag[7], ao[7];
        {
            float4 bb = g_packBias[t];
            u64 bi = dup2(bb.x), bf = dup2(bb.y), bg = dup2(bb.z), bo = dup2(bb.w);
            #pragma unroll
            for (int p = 0; p < 7; p++) { ai[p] = bi; af[p] = bf; ag[p] = bg; ao[p] = bo; }
            #pragma unroll
            for (int e = 0; e < 3; e++) {
                float4 we = g_packWih[e * 256 + t];
                u64 wx = dup2(we.x), wy = dup2(we.y), wz = dup2(we.z), ww = dup2(we.w);
                #pragma unroll
                for (int p = 0; p < 7; p++) {
                    u64 xp = *reinterpret_cast<const u64*>(&xs[e][2 * p]);
                    ai[p] = fma2(xp, wx, ai[p]);
                    af[p] = fma2(xp, wy, af[p]);
                    ag[p] = fma2(xp, wz, ag[p]);
                    ao[p] = fma2(xp, ww, ao[p]);
                }
            }
        }
        {
            const float4* wp   = g_packWhh + t;
            const float*  hrow = &h2[cur][0][0];
            #pragma unroll 2
            for (int k = 0; k < 256; k++) {
                float4 w = wp[k * 256];
                u64 wx = dup2(w.x), wy = dup2(w.y), wz = dup2(w.z), ww = dup2(w.w);
                const u64* hp = reinterpret_cast<const u64*>(hrow + k * HS);
                #pragma unroll
                for (int p = 0; p < 7; p++) {
                    u64 h = hp[p];
                    ai[p] = fma2(h, wx, ai[p]);
                    af[p] = fma2(h, wy, af[p]);
                    ag[p] = fma2(h, wz, ag[p]);
                    ao[p] = fma2(h, ww, ao[p]);
                }
            }
        }

        // ---- elementwise LSTM cell update: write new h into the OTHER buffer ----
        #pragma unroll
        for (int p = 0; p < 7; p++) {
            float2 iv = unpk(ai[p]), fv = unpk(af[p]);
            float2 gv = unpk(ag[p]), ov = unpk(ao[p]);
            float2 cv = unpk(c2[p]);
            float c0n = sigmoidf_(fv.x) * cv.x + sigmoidf_(iv.x) * tanhf_(gv.x);
            float c1n = sigmoidf_(fv.y) * cv.y + sigmoidf_(iv.y) * tanhf_(gv.y);
            h2[nxt][t][2 * p]     = sigmoidf_(ov.x) * tanhf_(c0n);
            h2[nxt][t][2 * p + 1] = sigmoidf_(ov.y) * tanhf_(c1n);
            c2[p] = pk(c0n, c1n);
        }
        __syncthreads();   // S1: new h visible; everyone done reading xs

        // ---- decoder layer 1: z = relu(h . Wo1^T + bo1)  (threads 0..127) ----
        if (t < 128) {
            u64 z[7];
            u64 bz = dup2(bo1s[t]);
            #pragma unroll
            for (int p = 0; p < 7; p++) z[p] = bz;
            const float* wo    = g_Wo1T + t;
            const float* hrow2 = &h2[nxt][0][0];
            #pragma unroll 2
            for (int k = 0; k < 256; k++) {
                u64 w = dup2(wo[k * 128]);
                const u64* hp = reinterpret_cast<const u64*>(hrow2 + k * HS);
                #pragma unroll
                for (int p = 0; p < 7; p++) z[p] = fma2(hp[p], w, z[p]);
            }
            #pragma unroll
            for (int p = 0; p < 7; p++) {
                float2 zv = unpk(z[p]);
                zb[2 * p][t]     = fmaxf(zv.x, 0.f);
                zb[2 * p + 1][t] = fmaxf(zv.y, 0.f);
            }
        }
        __syncthreads();   // S2: zb ready

        // ---- decoder layer 2: y = z . Wo2^T + bo2 ; feed back as next x ----
        if (t < 42) {
            int r = t / 3, o = t - 3 * (t / 3);
            float acc = bo2s[o];
            const float* zr = zb[r];
            const float* w2 = &wo2s[o * 128];
            #pragma unroll 8
            for (int j = 0; j < 128; j++) acc += zr[j] * w2[j];
            if (row0 + r < B_) outp[r * (T_eff * 3) + step * 3 + o] = acc;
            xs[o][r] = acc;
        }
        __syncthreads();   // S3: xs ready for next step

        cur = nxt;
    }
}

// ---------------------------------------------------------------------------
// Launch
// ---------------------------------------------------------------------------
extern "C" void kernel_launch(void* const* d_in, const int* in_sizes, int n_in,
                              void* d_out, int out_size)
{
    const float* meta = (const float*)d_in[0];
    // d_in[1] = target_seq_len (int32 scalar on device; out_size = B*T*3 encodes it)
    const float* W1   = (const float*)d_in[2];
    const float* b1   = (const float*)d_in[3];
    const float* W2   = (const float*)d_in[4];
    const float* b2   = (const float*)d_in[5];
    const float* Wih  = (const float*)d_in[6];
    const float* Whh  = (const float*)d_in[7];
    const float* bih  = (const float*)d_in[8];
    const float* bhh  = (const float*)d_in[9];
    const float* Wo1  = (const float*)d_in[10];
    const float* bo1  = (const float*)d_in[11];
    const float* Wo2  = (const float*)d_in[12];
    const float* bo2  = (const float*)d_in[13];
    float* out = (float*)d_out;

    int T_eff = out_size / (B_ * 3);   // equals target_seq_len by output shape

    prep_kernel<<<256, 256>>>(W1, W2, Wih, Whh, bih, bhh, Wo1);
    lstm_kernel<<<NCTA, 256>>>(meta, b1, b2, bo1, Wo2, bo2, out, T_eff);
}

// round 7
// speedup vs baseline: 1.2820x; 1.2820x over previous
#include <cuda_runtime.h>

// Problem constants (fixed by the dataset)
#define B_   4096
#define H_   256
#define R_   14              // rows per CTA
#define NCTA 293             // ceil(4096/14)
#define HS   18              // h2 row stride in floats (72B, 8B-aligned u64 reads)

// ---------------------------------------------------------------------------
// Device scratch (no dynamic allocation allowed)
// ---------------------------------------------------------------------------
__device__ float4 g_packWhh[256 * 256];  // [k][j] -> (Whh_i, Whh_f, Whh_g, Whh_o)[j][k]
__device__ float4 g_packWih[3 * 256];    // [e][j]
__device__ float4 g_packBias[256];       // [j]    -> bih+bhh per gate
__device__ float  g_W2T[256 * 512];      // [k][j]
__device__ float  g_Wo1T[256 * 128];     // [k][j2]
__device__ float  g_W1T[7 * 256];        // [k][j]

// ---------------------------------------------------------------------------
// Prep kernel: transpose / gate-pack weights for coalesced LDG.128 streaming
// ---------------------------------------------------------------------------
__global__ void prep_kernel(const float* __restrict__ W1,
                            const float* __restrict__ W2,
                            const float* __restrict__ Wih,
                            const float* __restrict__ Whh,
                            const float* __restrict__ bih,
                            const float* __restrict__ bhh,
                            const float* __restrict__ Wo1)
{
    int k = blockIdx.x;    // 0..255
    int j = threadIdx.x;   // 0..255

    g_packWhh[k * 256 + j] = make_float4(Whh[(0   + j) * 256 + k],
                                         Whh[(256 + j) * 256 + k],
                                         Whh[(512 + j) * 256 + k],
                                         Whh[(768 + j) * 256 + k]);
    g_W2T[k * 512 + j]       = W2[(0   + j) * 256 + k];
    g_W2T[k * 512 + 256 + j] = W2[(256 + j) * 256 + k];
    if (j < 128) g_Wo1T[k * 128 + j] = Wo1[j * 256 + k];
    if (k < 7)   g_W1T[k * 256 + j] = W1[j * 7 + k];
    if (k < 3)   g_packWih[k * 256 + j] = make_float4(Wih[(0   + j) * 3 + k],
                                                      Wih[(256 + j) * 3 + k],
                                                      Wih[(512 + j) * 3 + k],
                                                      Wih[(768 + j) * 3 + k]);
    if (k == 0)  g_packBias[j] = make_float4(bih[0   + j] + bhh[0   + j],
                                             bih[256 + j] + bhh[256 + j],
                                             bih[512 + j] + bhh[512 + j],
                                             bih[768 + j] + bhh[768 + j]);
}

// ---------------------------------------------------------------------------
// Packed f32x2 helpers (sm_100+): doubles fp32 FMA throughput per issue
// ---------------------------------------------------------------------------
typedef unsigned long long u64;

__device__ __forceinline__ u64 fma2(u64 a, u64 b, u64 c) {
    u64 d;
    asm("fma.rn.f32x2 %0, %1, %2, %3;" : "=l"(d) : "l"(a), "l"(b), "l"(c));
    return d;
}
__device__ __forceinline__ u64 dup2(float x) {
    u64 d; unsigned xi = __float_as_uint(x);
    asm("mov.b64 %0, {%1, %2};" : "=l"(d) : "r"(xi), "r"(xi));
    return d;
}
__device__ __forceinline__ u64 pk(float lo, float hi) {
    u64 d;
    asm("mov.b64 %0, {%1, %2};" : "=l"(d)
        : "r"(__float_as_uint(lo)), "r"(__float_as_uint(hi)));
    return d;
}
__device__ __forceinline__ float2 unpk(u64 a) {
    unsigned lo, hi;
    asm("mov.b64 {%0, %1}, %2;" : "=r"(lo), "=r"(hi) : "l"(a));
    return make_float2(__uint_as_float(lo), __uint_as_float(hi));
}

__device__ __forceinline__ float sigmoidf_(float x) {
    return __fdividef(1.f, 1.f + __expf(-x));
}
// branch-free accurate tanh: 1 - 2/(e^{2x}+1); inf-safe, ~1e-6 err
__device__ __forceinline__ float tanhf_(float x) {
    float e = __expf(2.f * x);
    return 1.f - __fdividef(2.f, e + 1.f);
}

// One k-slice of the 4-gate MAC: 4 dups + 7 h loads + 28 fma2
__device__ __forceinline__ void mac_k(const float4 w, const float* __restrict__ hb,
                                      u64* ai, u64* af, u64* ag, u64* ao)
{
    u64 wx = dup2(w.x), wy = dup2(w.y), wz = dup2(w.z), ww = dup2(w.w);
    #pragma unroll
    for (int p = 0; p < 7; p++) {
        u64 h = *reinterpret_cast<const u64*>(hb + 2 * p);
        ai[p] = fma2(h, wx, ai[p]);
        af[p] = fma2(h, wy, af[p]);
        ag[p] = fma2(h, wz, ag[p]);
        ao[p] = fma2(h, ww, ao[p]);
    }
}

// ---------------------------------------------------------------------------
// Main persistent kernel: one CTA handles 14 batch rows end-to-end.
// ---------------------------------------------------------------------------
__global__ void __launch_bounds__(256, 2)
lstm_kernel(const float* __restrict__ meta,
            const float* __restrict__ b1,
            const float* __restrict__ b2,
            const float* __restrict__ bo1,
            const float* __restrict__ Wo2,
            const float* __restrict__ bo2,
            float* __restrict__ out,
            int T_eff)
{
    __shared__ __align__(16) float h2[2][256][HS]; // double-buffered h [buf][k][row]
    __shared__ __align__(16) float xs[3][16];      // [elem][row] current x (fed-back y)
    __shared__ __align__(16) float zb[14][132];    // decoder hidden [row][j2]
    __shared__ float metas[14][8];
    __shared__ __align__(16) float wo2s[3 * 128];
    __shared__ float bo1s[128];
    __shared__ float bo2s[4];

    const int t    = threadIdx.x;
    const int row0 = blockIdx.x * R_;

    // ---- stage small tensors (row indices clamped for the partial last CTA) ----
    if (t < 112) {
        int r = t >> 3, e = t & 7;
        int g = row0 + r; if (g > B_ - 1) g = B_ - 1;
        metas[r][e] = (e < 7) ? meta[g * 7 + e] : 0.f;
    }
    if (t < 128) bo1s[t] = bo1[t];
    wo2s[t] = Wo2[t];
    if (t < 128) wo2s[256 + t] = Wo2[256 + t];
    if (t < 3)   bo2s[t] = bo2[t];
    if (t < 42) {
        int r = t / 3, o = t - 3 * (t / 3);
        int g = row0 + r; if (g > B_ - 1) g = B_ - 1;
        xs[o][r] = meta[g * 7 + o];   // x0 = metadata[:, :3]
    }
    __syncthreads();

    // ---- encoder layer 1: enc1 -> h2[1][t][r] ----
    {
        float a[R_];
        float bb = b1[t];
        #pragma unroll
        for (int r = 0; r < R_; r++) a[r] = bb;
        #pragma unroll
        for (int k = 0; k < 7; k++) {
            float w = g_W1T[k * 256 + t];
            #pragma unroll
            for (int r = 0; r < R_; r++) a[r] += metas[r][k] * w;
        }
        #pragma unroll
        for (int r = 0; r < R_; r++) h2[1][t][r] = fmaxf(a[r], 0.f);
    }
    __syncthreads();

    // ---- encoder layer 2: h0 -> h2[0], c0 in regs ----
    u64 c2[7];
    {
        u64 ha[7], ca[7];
        u64 bh = dup2(b2[t]), bc = dup2(b2[256 + t]);
        #pragma unroll
        for (int p = 0; p < 7; p++) { ha[p] = bh; ca[p] = bc; }
        const float* hrow = &h2[1][0][0];
        #pragma unroll 2
        for (int k = 0; k < 256; k++) {
            u64 wh = dup2(g_W2T[k * 512 + t]);
            u64 wc = dup2(g_W2T[k * 512 + 256 + t]);
            const u64* hp = reinterpret_cast<const u64*>(hrow + k * HS);
            #pragma unroll
            for (int p = 0; p < 7; p++) {
                u64 h = hp[p];
                ha[p] = fma2(h, wh, ha[p]);
                ca[p] = fma2(h, wc, ca[p]);
            }
        }
        #pragma unroll
        for (int p = 0; p < 7; p++) {
            float2 hv = unpk(ha[p]);
            float2 cv = unpk(ca[p]);
            h2[0][t][2 * p]     = fmaxf(hv.x, 0.f);
            h2[0][t][2 * p + 1] = fmaxf(hv.y, 0.f);
            c2[p] = pk(fmaxf(cv.x, 0.f), fmaxf(cv.y, 0.f));
        }
    }
    __syncthreads();

    const int j2 = t & 127;
    const int hi = t >> 7;
    const int p0 = hi ? 4 : 0;        // decoder row-pair window [p0, p0+np)
    const int np = hi ? 3 : 4;
    float* outp = out + (long)row0 * (T_eff * 3);
    int cur = 0;

    // =====================  LSTM scan  =====================
    for (int step = 0; step < T_eff; step++) {
        const int nxt = cur ^ 1;

        // ---- gate accumulation: gates[j] = bias + x.Wih + h.Whh ----
        u64 ai[7], af[7], ag[7], ao[7];
        {
            float4 bb = g_packBias[t];
            u64 bi = dup2(bb.x), bf = dup2(bb.y), bg = dup2(bb.z), bo = dup2(bb.w);
            #pragma unroll
            for (int p = 0; p < 7; p++) { ai[p] = bi; af[p] = bf; ag[p] = bg; ao[p] = bo; }
            #pragma unroll
            for (int e = 0; e < 3; e++) {
                float4 we = g_packWih[e * 256 + t];
                u64 wx = dup2(we.x), wy = dup2(we.y), wz = dup2(we.z), ww = dup2(we.w);
                #pragma unroll
                for (int p = 0; p < 7; p++) {
                    u64 xp = *reinterpret_cast<const u64*>(&xs[e][2 * p]);
                    ai[p] = fma2(xp, wx, ai[p]);
                    af[p] = fma2(xp, wy, af[p]);
                    ag[p] = fma2(xp, wz, ag[p]);
                    ao[p] = fma2(xp, ww, ao[p]);
                }
            }
        }
        {
            // k-blocks of 4 with front-batched weight LDG.128s (MLP=4/warp)
            const float4* wp   = g_packWhh + t;
            const float*  hrow = &h2[cur][0][0];
            #pragma unroll 1
            for (int kb = 0; kb < 256; kb += 4) {
                float4 w0 = wp[(kb + 0) * 256];
                float4 w1 = wp[(kb + 1) * 256];
                float4 w2 = wp[(kb + 2) * 256];
                float4 w3 = wp[(kb + 3) * 256];
                const float* hb = hrow + kb * HS;
                mac_k(w0, hb,          ai, af, ag, ao);
                mac_k(w1, hb + HS,     ai, af, ag, ao);
                mac_k(w2, hb + 2 * HS, ai, af, ag, ao);
                mac_k(w3, hb + 3 * HS, ai, af, ag, ao);
            }
        }

        // ---- elementwise LSTM cell update: write new h into the OTHER buffer ----
        #pragma unroll
        for (int p = 0; p < 7; p++) {
            float2 iv = unpk(ai[p]), fv = unpk(af[p]);
            float2 gv = unpk(ag[p]), ov = unpk(ao[p]);
            float2 cv = unpk(c2[p]);
            float c0n = sigmoidf_(fv.x) * cv.x + sigmoidf_(iv.x) * tanhf_(gv.x);
            float c1n = sigmoidf_(fv.y) * cv.y + sigmoidf_(iv.y) * tanhf_(gv.y);
            h2[nxt][t][2 * p]     = sigmoidf_(ov.x) * tanhf_(c0n);
            h2[nxt][t][2 * p + 1] = sigmoidf_(ov.y) * tanhf_(c1n);
            c2[p] = pk(c0n, c1n);
        }
        __syncthreads();   // S1: new h visible; everyone done reading xs

        // ---- decoder layer 1 (ALL 256 threads): z = relu(h . Wo1^T + bo1) ----
        {
            u64 z[4];
            u64 bz = dup2(bo1s[j2]);
            #pragma unroll
            for (int p = 0; p < 4; p++) z[p] = bz;
            const float* wo    = g_Wo1T + j2;
            const float* hrow2 = &h2[nxt][0][0] + 2 * p0;
            #pragma unroll 1
            for (int kb = 0; kb < 256; kb += 8) {
                float w0 = wo[(kb + 0) * 128];
                float w1 = wo[(kb + 1) * 128];
                float w2 = wo[(kb + 2) * 128];
                float w3 = wo[(kb + 3) * 128];
                float w4 = wo[(kb + 4) * 128];
                float w5 = wo[(kb + 5) * 128];
                float w6 = wo[(kb + 6) * 128];
                float w7 = wo[(kb + 7) * 128];
                float wv[8] = {w0, w1, w2, w3, w4, w5, w6, w7};
                #pragma unroll
                for (int i = 0; i < 8; i++) {
                    u64 wd = dup2(wv[i]);
                    const float* hb = hrow2 + (kb + i) * HS;
                    #pragma unroll
                    for (int p = 0; p < 4; p++)
                        if (p < np)
                            z[p] = fma2(*reinterpret_cast<const u64*>(hb + 2 * p), wd, z[p]);
                }
            }
            #pragma unroll
            for (int p = 0; p < 4; p++)
                if (p < np) {
                    float2 zv = unpk(z[p]);
                    zb[2 * (p0 + p)][j2]     = fmaxf(zv.x, 0.f);
                    zb[2 * (p0 + p) + 1][j2] = fmaxf(zv.y, 0.f);
                }
        }
        __syncthreads();   // S2: zb ready

        // ---- decoder layer 2: y = z . Wo2^T + bo2 ; feed back as next x ----
        if (t < 42) {
            int r = t / 3, o = t - 3 * (t / 3);
            const float* zr = zb[r];
            const float* w2 = &wo2s[o * 128];
            float4 acc4 = make_float4(0.f, 0.f, 0.f, 0.f);
            #pragma unroll 8
            for (int j = 0; j < 128; j += 4) {
                float4 zv = *reinterpret_cast<const float4*>(zr + j);
                float4 wv = *reinterpret_cast<const float4*>(w2 + j);
                acc4.x += zv.x * wv.x;
                acc4.y += zv.y * wv.y;
                acc4.z += zv.z * wv.z;
                acc4.w += zv.w * wv.w;
            }
            float acc = bo2s[o] + ((acc4.x + acc4.y) + (acc4.z + acc4.w));
            if (row0 + r < B_) outp[r * (T_eff * 3) + step * 3 + o] = acc;
            xs[o][r] = acc;
        }
        __syncthreads();   // S3: xs ready for next step

        cur = nxt;
    }
}

// ---------------------------------------------------------------------------
// Launch
// ---------------------------------------------------------------------------
extern "C" void kernel_launch(void* const* d_in, const int* in_sizes, int n_in,
                              void* d_out, int out_size)
{
    const float* meta = (const float*)d_in[0];
    // d_in[1] = target_seq_len (encoded by the output shape)
    const float* W1   = (const float*)d_in[2];
    const float* b1   = (const float*)d_in[3];
    const float* W2   = (const float*)d_in[4];
    const float* b2   = (const float*)d_in[5];
    const float* Wih  = (const float*)d_in[6];
    const float* Whh  = (const float*)d_in[7];
    const float* bih  = (const float*)d_in[8];
    const float* bhh  = (const float*)d_in[9];
    const float* Wo1  = (const float*)d_in[10];
    const float* bo1  = (const float*)d_in[11];
    const float* Wo2  = (const float*)d_in[12];
    const float* bo2  = (const float*)d_in[13];
    float* out = (float*)d_out;

    int T_eff = out_size / (B_ * 3);   // equals target_seq_len by output shape

    prep_kernel<<<256, 256>>>(W1, W2, Wih, Whh, bih, bhh, Wo1);
    lstm_kernel<<<NCTA, 256>>>(meta, b1, b2, bo1, Wo2, bo2, out, T_eff);
}